// round 2
// baseline (speedup 1.0000x reference)
#include <cuda_runtime.h>

#define NB 16
#define CH 256
#define KS 6
#define MS 22
#define HO 17                      // MS - KS + 1
#define OUT_PER_N (HO*HO)          // 289
#define TOT_OUT (NB*OUT_PER_N)     // 4624
#define CPB 16                     // channels per block
#define NCHUNK (CH/CPB)            // 16
#define RS 25                      // padded smem row stride (25 coprime 32 -> conflict-free row loads)
#define CSTR (MS*RS)               // 550 floats per channel tile
#define TPB (HO*CPB)               // 272 threads

// scratch (no allocations allowed -> device globals)
__device__ float g_partial[NCHUNK * TOT_OUT];   // [chunk][n*289 + out]
__device__ float g_mean[TOT_OUT];               // mean_coeff, flattened [n][oy][ox]

__device__ __forceinline__ float fsqrt_fast(float a) {
    float r; asm("sqrt.approx.f32 %0, %1;" : "=f"(r) : "f"(a)); return r;
}

// ---------------------------------------------------------------------------
// Kernel 1: per-(n, channel-chunk) sliding-window correlation.
// Each thread owns one output row (17 accumulators) for one channel lane.
// x/z are sqrt'ed on the gmem->smem path (each element read from HBM once).
// ---------------------------------------------------------------------------
__global__ __launch_bounds__(TPB) void corr_kernel(
    const float* __restrict__ z, const float* __restrict__ x,
    const float* __restrict__ w)
{
    __shared__ float xs[CPB * CSTR];      // 8800 floats (35.2 KB), reused for reduction
    __shared__ float zs[CPB * KS * KS];   // 576 floats

    const int chunk = blockIdx.x;
    const int n     = blockIdx.y;
    const int t     = threadIdx.x;

    // --- cooperative load with fused sqrt ---
    const float* xg = x + (size_t)(n * CH + chunk * CPB) * (MS * MS);
    for (int e = t; e < CPB * MS * MS; e += TPB) {
        int cl  = e / (MS * MS);
        int rem = e - cl * (MS * MS);
        int r   = rem / MS;
        int col = rem - r * MS;
        xs[cl * CSTR + r * RS + col] = fsqrt_fast(xg[e]);
    }
    const float* zg = z + (size_t)(n * CH + chunk * CPB) * (KS * KS);
    for (int e = t; e < CPB * KS * KS; e += TPB) {
        int cl = e / (KS * KS);
        zs[e] = fsqrt_fast(zg[e]) * w[chunk * CPB + cl];
    }
    __syncthreads();

    // --- compute: thread = (oy, channel lane); slide 6-tap filter over a row ---
    const int oy = t % HO;
    const int cl = t / HO;
    const float* xb = &xs[cl * CSTR];
    const float* zb = &zs[cl * KS * KS];

    float acc[HO];
#pragma unroll
    for (int i = 0; i < HO; i++) acc[i] = 0.f;

#pragma unroll
    for (int k1 = 0; k1 < KS; k1++) {
        float xr[MS];
#pragma unroll
        for (int j = 0; j < MS; j++) xr[j] = xb[(oy + k1) * RS + j];
#pragma unroll
        for (int k2 = 0; k2 < KS; k2++) {
            float zv = zb[k1 * KS + k2];
#pragma unroll
            for (int ox = 0; ox < HO; ox++)
                acc[ox] = fmaf(xr[ox + k2], zv, acc[ox]);
        }
    }

    // --- reduce 16 channel lanes (reuse xs as scratch; fixed order) ---
    __syncthreads();
#pragma unroll
    for (int ox = 0; ox < HO; ox++)
        xs[cl * CSTR + oy * HO + ox] = acc[ox];
    __syncthreads();

    // NOTE: OUT_PER_N (289) > TPB (272) -> strided loop, not a single guard.
    for (int idx = t; idx < OUT_PER_N; idx += TPB) {
        float s = 0.f;
#pragma unroll
        for (int c2 = 0; c2 < CPB; c2++) s += xs[c2 * CSTR + idx];
        g_partial[chunk * TOT_OUT + n * OUT_PER_N + idx] = s;
    }
}

// ---------------------------------------------------------------------------
// Kernel 2: sum the 16 channel-chunk partials, apply the 1/36 kernel-mean.
// ---------------------------------------------------------------------------
__global__ void chunk_reduce()
{
    int idx = blockIdx.x * blockDim.x + threadIdx.x;
    if (idx < TOT_OUT) {
        float s = 0.f;
#pragma unroll
        for (int ch = 0; ch < NCHUNK; ch++) s += g_partial[ch * TOT_OUT + idx];
        g_mean[idx] = s * (1.f / (KS * KS));
    }
}

// ---------------------------------------------------------------------------
// Kernel 3: single-block BatchNorm over all 4624 values (two-pass: exact
// mean, then centered variance -> no catastrophic cancellation).
// ---------------------------------------------------------------------------
__global__ __launch_bounds__(512) void finalize(
    float* __restrict__ out,
    const float* __restrict__ bw, const float* __restrict__ bb)
{
    __shared__ float sred[512];
    __shared__ float s_mu, s_scale;
    const int t = threadIdx.x;

    float v[10];
    float lsum = 0.f;
#pragma unroll
    for (int k = 0; k < 10; k++) {
        int idx = t + k * 512;
        v[k] = (idx < TOT_OUT) ? g_mean[idx] : 0.f;
        lsum += v[k];
    }
    sred[t] = lsum; __syncthreads();
    for (int s = 256; s > 0; s >>= 1) { if (t < s) sred[t] += sred[t + s]; __syncthreads(); }
    if (t == 0) s_mu = sred[0] / (float)TOT_OUT;
    __syncthreads();
    const float mu = s_mu;

    float lss = 0.f;
#pragma unroll
    for (int k = 0; k < 10; k++) {
        int idx = t + k * 512;
        if (idx < TOT_OUT) { float d = v[k] - mu; lss += d * d; }
    }
    sred[t] = lss; __syncthreads();
    for (int s = 256; s > 0; s >>= 1) { if (t < s) sred[t] += sred[t + s]; __syncthreads(); }
    if (t == 0) s_scale = rsqrtf(sred[0] / (float)TOT_OUT + 1e-5f) * bw[0];
    __syncthreads();
    const float scale = s_scale;
    const float bias  = bb[0];

#pragma unroll
    for (int k = 0; k < 10; k++) {
        int idx = t + k * 512;
        if (idx < TOT_OUT) out[idx] = (v[k] - mu) * scale + bias;
    }
}

extern "C" void kernel_launch(void* const* d_in, const int* in_sizes, int n_in,
                              void* d_out, int out_size)
{
    // default: dict order z, x, weights, bn_weight, bn_bias
    const float* z  = (const float*)d_in[0];
    const float* x  = (const float*)d_in[1];
    const float* w  = (const float*)d_in[2];
    const float* bw = (const float*)d_in[3];
    const float* bb = (const float*)d_in[4];

    // robust identification by element count (bn_weight/bias both size 1: keep order)
    int first_one = -1;
    for (int i = 0; i < n_in; i++) {
        if (in_sizes[i] == NB * CH * KS * KS)      z = (const float*)d_in[i];
        else if (in_sizes[i] == NB * CH * MS * MS) x = (const float*)d_in[i];
        else if (in_sizes[i] == CH)                w = (const float*)d_in[i];
        else if (in_sizes[i] == 1) {
            if (first_one < 0) { bw = (const float*)d_in[i]; first_one = i; }
            else                 bb = (const float*)d_in[i];
        }
    }

    dim3 grid(NCHUNK, NB);                       // 16 x 16 = 256 blocks
    corr_kernel<<<grid, TPB>>>(z, x, w);
    chunk_reduce<<<(TOT_OUT + 255) / 256, 256>>>();
    finalize<<<1, 512>>>((float*)d_out, bw, bb);
}